// round 8
// baseline (speedup 1.0000x reference)
#include <cuda_runtime.h>
#include <cstdint>

#define BT   64
#define P    68
#define NTHR 256
typedef unsigned long long ull;

// ---------------- persistent device scratch ----------------
__device__ __align__(16) float g_W1T[784*128];   // [k][j]
__device__ __align__(16) float g_M1T[128*128];   // -(W1@fb1)^T k-major, plain
__device__ __align__(16) float g_U1T[128*128];   // plain k-major
__device__ __align__(16) float g_W22T[192*64];   // rows 0-127: W2T, rows 128-191: -M2T
__device__ __align__(16) float g_U2T[64*64];
__device__ __align__(16) float g_L3[4096];       // rows0-63 W3T[.][32] | rows64-95 -M3T | U3T[32][32]
__device__ __align__(16) float g_c1[128];
__device__ __align__(16) float g_c2[64];
__device__ __align__(16) float g_c3[32];

// ---------------- helpers ----------------
__device__ __forceinline__ ull dup2(float x) {
    ull r; asm("mov.b64 %0, {%1, %1};" : "=l"(r) : "f"(x)); return r;
}
__device__ __forceinline__ void up2(ull v, float &lo, float &hi) {
    asm("mov.b64 {%0, %1}, %2;" : "=f"(lo), "=f"(hi) : "l"(v));
}
__device__ __forceinline__ void fma2(ull &d, ull a, ull b) {
    asm("fma.rn.f32x2 %0, %1, %2, %0;" : "+l"(d) : "l"(a), "l"(b));
}
// tanh(x) = 1 - 2/(1+e^{2x})  via MUFU.EX2 + MUFU.RCP (~1e-6 abs err)
__device__ __forceinline__ float ftanh(float x) {
    float e, r;
    asm("ex2.approx.ftz.f32 %0, %1;" : "=f"(e) : "f"(x * 2.8853900817779268f));
    asm("rcp.approx.ftz.f32 %0, %1;" : "=f"(r) : "f"(e + 1.0f));
    return fmaf(-2.0f, r, 1.0f);
}
__device__ __forceinline__ void addf4(float4 &v, int r, float d) {
    if (r == 0) v.x += d; else if (r == 1) v.y += d;
    else if (r == 2) v.z += d; else v.w += d;
}

// L1 dual GEMM with DIRECT GLOBAL B (L2-resident weights), K=128.
// Thread: 8 rows (i0..i0+7) x 4 cols (j4..j4+3) per matrix.
__device__ __forceinline__ void gemmL1G(const float* __restrict__ A,
                                        const float* __restrict__ Bm,
                                        const float* __restrict__ Bu,
                                        int i0, int j4, ull (&m)[8][2], ull (&u)[8][2]) {
#pragma unroll 2
    for (int k = 0; k < 128; k++) {
        ulonglong2 bm = *reinterpret_cast<const ulonglong2*>(Bm + k * 128 + j4);
        ulonglong2 bu = *reinterpret_cast<const ulonglong2*>(Bu + k * 128 + j4);
        float4 a0 = *reinterpret_cast<const float4*>(A + k * P + i0);
        float4 a1 = *reinterpret_cast<const float4*>(A + k * P + i0 + 4);
        ull Ar[8] = {dup2(a0.x), dup2(a0.y), dup2(a0.z), dup2(a0.w),
                     dup2(a1.x), dup2(a1.y), dup2(a1.z), dup2(a1.w)};
#pragma unroll
        for (int r = 0; r < 8; r++) {
            fma2(m[r][0], Ar[r], bm.x);
            fma2(m[r][1], Ar[r], bm.y);
            fma2(u[r][0], Ar[r], bu.x);
            fma2(u[r][1], Ar[r], bu.y);
        }
    }
}

// 8 rows x 2 cols (1 f32x2) single-B GEMM, B in smem panel
template<int K, int LDB, int UNR>
__device__ __forceinline__ void gemmR8(const float* __restrict__ A,
                                       const float* __restrict__ B,
                                       int i0, int j, ull (&acc)[8]) {
#pragma unroll UNR
    for (int k = 0; k < K; k++) {
        float4 a0 = *reinterpret_cast<const float4*>(A + k * P + i0);
        float4 a1 = *reinterpret_cast<const float4*>(A + k * P + i0 + 4);
        ull b = *reinterpret_cast<const ull*>(B + k * LDB + j);
        ull Ar[8] = {dup2(a0.x), dup2(a0.y), dup2(a0.z), dup2(a0.w),
                     dup2(a1.x), dup2(a1.y), dup2(a1.z), dup2(a1.w)};
#pragma unroll
        for (int r = 0; r < 8; r++) fma2(acc[r], Ar[r], b);
    }
}

// 4 rows x 2 cols single-B GEMM
template<int K, int LDB, int UNR>
__device__ __forceinline__ void gemmR4(const float* __restrict__ A,
                                       const float* __restrict__ B,
                                       int i0, int j, ull (&acc)[4]) {
#pragma unroll UNR
    for (int k = 0; k < K; k++) {
        float4 a = *reinterpret_cast<const float4*>(A + k * P + i0);
        ull b = *reinterpret_cast<const ull*>(B + k * LDB + j);
        ull Ar[4] = {dup2(a.x), dup2(a.y), dup2(a.z), dup2(a.w)};
#pragma unroll
        for (int r = 0; r < 4; r++) fma2(acc[r], Ar[r], b);
    }
}

// 2048-float panel staging: 2 float4 per thread (halves at +0 and +1024 floats)
__device__ __forceinline__ void pld(const float* __restrict__ src, int tid, float4 (&r)[2]) {
    r[0] = *reinterpret_cast<const float4*>(src + tid * 4);
    r[1] = *reinterpret_cast<const float4*>(src + 1024 + tid * 4);
}
__device__ __forceinline__ void pst(float* dst, int tid, const float4 (&r)[2]) {
    *reinterpret_cast<float4*>(dst + tid * 4) = r[0];
    *reinterpret_cast<float4*>(dst + 1024 + tid * 4) = r[1];
}

// ---------------- prep kernel ----------------
__global__ void prep_all(const float* __restrict__ W1w, const float* __restrict__ W1b,
                         const float* __restrict__ U1w,
                         const float* __restrict__ W2w, const float* __restrict__ W2b,
                         const float* __restrict__ U2w,
                         const float* __restrict__ W3w, const float* __restrict__ W3b,
                         const float* __restrict__ U3w,
                         const float* __restrict__ fb3w, const float* __restrict__ fb3b,
                         const float* __restrict__ fb2w, const float* __restrict__ fb2b,
                         const float* __restrict__ fb1w, const float* __restrict__ fb1b) {
    __shared__ float row_s[784];
    __shared__ float red_s[128];
    const int bid = blockIdx.x;
    const int tid = threadIdx.x;   // 128

    if (bid < 128) {
        const int j = bid;
        for (int d = tid; d < 784; d += 128) row_s[d] = W1w[j * 784 + d];
        __syncthreads();
        {
            const int k = tid;
            float s = 0.f;
#pragma unroll 4
            for (int d = 0; d < 784; d++) s += row_s[d] * fb1w[d * 128 + k];
            g_M1T[k * 128 + j] = -s;
        }
        float ps = 0.f;
        for (int d = tid; d < 784; d += 128) ps += row_s[d] * fb1b[d];
        red_s[tid] = ps;
        __syncthreads();
        for (int off = 64; off > 0; off >>= 1) {
            if (tid < off) red_s[tid] += red_s[tid + off];
            __syncthreads();
        }
        if (tid == 0) g_c1[j] = W1b[j] - red_s[0];
    } else if (bid < 192) {
        const int j = bid - 128;
        for (int d = tid; d < 128; d += 128) row_s[d] = W2w[j * 128 + d];
        __syncthreads();
        if (tid < 64) {
            const int k = tid;
            float s = 0.f;
#pragma unroll 4
            for (int d = 0; d < 128; d++) s += row_s[d] * fb2w[d * 64 + k];
            g_W22T[(128 + k) * 64 + j] = -s;   // -M2T rows of stacked weight
        }
        float ps = 0.f;
        for (int d = tid; d < 128; d += 128) ps += row_s[d] * fb2b[d];
        red_s[tid] = ps;
        __syncthreads();
        for (int off = 64; off > 0; off >>= 1) {
            if (tid < off) red_s[tid] += red_s[tid + off];
            __syncthreads();
        }
        if (tid == 0) g_c2[j] = W2b[j] - red_s[0];
    } else if (bid < 224) {
        const int j = bid - 192;
        for (int d = tid; d < 64; d += 128) row_s[d] = W3w[j * 64 + d];
        __syncthreads();
        if (tid < 32) {
            const int k = tid;
            float s = 0.f;
#pragma unroll 4
            for (int d = 0; d < 64; d++) s += row_s[d] * fb3w[d * 32 + k];
            g_L3[(64 + k) * 32 + j] = -s;    // -M3T rows of stacked weight
        }
        float ps = 0.f;
        for (int d = tid; d < 64; d += 128) ps += row_s[d] * fb3b[d];
        red_s[tid] = ps;
        __syncthreads();
        for (int off = 64; off > 0; off >>= 1) {
            if (tid < off) red_s[tid] += red_s[tid + off];
            __syncthreads();
        }
        if (tid == 0) g_c3[j] = W3b[j] - red_s[0];
    } else {
        const int idx0 = (bid - 224) * 128 + tid;
        const int stride = 32 * 128;
        for (int t = idx0; t < 784 * 128; t += stride) {
            int k = t >> 7, j = t & 127;
            g_W1T[t] = W1w[j * 784 + k];
        }
        for (int t = idx0; t < 128 * 128; t += stride) {          // U1T plain
            int k = t >> 7, j = t & 127;
            g_U1T[t] = U1w[j * 128 + k];
        }
        for (int t = idx0; t < 128 * 64; t += stride) {           // W2T rows of stacked
            int k = t >> 6, j = t & 63;
            g_W22T[t] = W2w[j * 128 + k];
        }
        for (int t = idx0; t < 64 * 64; t += stride) {
            int k = t >> 6, j = t & 63;
            g_U2T[t] = U2w[j * 64 + k];
        }
        for (int t = idx0; t < 64 * 32; t += stride) {            // W3T rows of stacked
            int k = t >> 5, j = t & 31;
            g_L3[t] = W3w[j * 64 + k];
        }
        for (int t = idx0; t < 32 * 32; t += stride) {            // U3T
            int k = t >> 5, j = t & 31;
            g_L3[3072 + t] = U3w[j * 32 + k];
        }
    }
}

// ---------------- main kernel ----------------
// smem floats (27840 total = 111360 B, 2 CTAs/SM):
//   h1s[128*68]@0  h2s[64*68]@8704  h3s[32*68]@13056  (contiguous -> concat-K gemms)
//   xws[64][128]@15232 (8192)  buf0@23424(2048)  buf1@25472(2048)  sB@27520(320)
// phase-1 overlay: xck@0 [64][116]=7424, wck@7424 [112][128] (ends 21760; reads finish
//   before xws writes each chunk's trailing barrier)
__global__ void __launch_bounds__(NTHR, 2)
pcnet_main(const float* __restrict__ x,
           const float* __restrict__ U1b, const float* __restrict__ U2b,
           const float* __restrict__ U3b,
           const float* __restrict__ clfw, const float* __restrict__ clfb,
           const int* __restrict__ steps_p,
           float* __restrict__ out) {
    extern __shared__ float sm[];
    float* h1s  = sm;
    float* h2s  = sm + 8704;
    float* h3s  = sm + 13056;
    float* xws  = sm + 15232;
    float* buf0 = sm + 23424;
    float* buf1 = sm + 25472;
    float* sB   = sm + 27520;
    float* xck  = sm;           // overlay
    float* wck  = sm + 7424;    // overlay

    const int tid  = threadIdx.x;
    const int row0 = blockIdx.x * BT;

    // tile mapping: warp spans 4 row-groups x 8 col-quads
    const int wid  = tid >> 5, lane = tid & 31;
    const int rg   = ((wid & 1) << 2) + (lane >> 3);   // 0..7
    const int cq   = ((wid >> 1) << 3) + (lane & 7);   // 0..31
    const int i0   = rg * 8;
    const int j4   = cq * 4;      // L1 cols
    const int j2   = cq * 2;      // L2 cols
    const int rg3  = ((wid & 3) << 2) + (lane >> 3);   // 0..15
    const int cq3  = ((wid >> 2) << 3) + (lane & 7);   // 0..15
    const int i03  = rg3 * 4;
    const int j3   = cq3 * 2;     // L3 cols

    int steps = *steps_p;
    if (steps < 0 || steps > 64) steps = 5;

    // stage biases + first panel (disjoint from phase-1 overlay)
    for (int t = tid; t < 320; t += NTHR) {
        float v;
        if (t < 32) v = g_c3[t];
        else if (t < 64) v = U3b[t - 32];
        else if (t < 128) v = g_c2[t - 64];
        else if (t < 192) v = U2b[t - 128];
        else v = U1b[t - 192];
        sB[t] = v;
    }
    for (int idx = tid; idx < 512; idx += NTHR)
        *reinterpret_cast<float4*>(buf0 + idx * 4) = *reinterpret_cast<const float4*>(g_L3 + idx * 4);

    // ---- phase 1: xw = x @ W1^T + c1 -> xws (4rx8c mapping) ----
    {
        const int p_i0 = (tid >> 4) * 4;
        const int p_j4 = (tid & 15) * 4;
        ull axw[4][4] = {};
        for (int c = 0; c < 7; c++) {
            for (int idx = tid; idx < 64 * 28; idx += NTHR) {
                int r = idx / 28, k4 = idx - r * 28;
                *reinterpret_cast<float4*>(xck + r * 116 + k4 * 4) =
                    *reinterpret_cast<const float4*>(x + (size_t)(row0 + r) * 784 + c * 112 + k4 * 4);
            }
            for (int idx = tid; idx < 112 * 32; idx += NTHR) {
                int kk = idx >> 5, jj = idx & 31;
                *reinterpret_cast<float4*>(wck + kk * 128 + jj * 4) =
                    *reinterpret_cast<const float4*>(g_W1T + (size_t)(c * 112 + kk) * 128 + jj * 4);
            }
            __syncthreads();
#pragma unroll 2
            for (int kk = 0; kk < 112; kk++) {
                ulonglong2 b0 = *reinterpret_cast<const ulonglong2*>(wck + kk * 128 + p_j4);
                ulonglong2 b1 = *reinterpret_cast<const ulonglong2*>(wck + kk * 128 + 64 + p_j4);
                ull Ar[4] = {dup2(xck[(p_i0 + 0) * 116 + kk]), dup2(xck[(p_i0 + 1) * 116 + kk]),
                             dup2(xck[(p_i0 + 2) * 116 + kk]), dup2(xck[(p_i0 + 3) * 116 + kk])};
#pragma unroll
                for (int r = 0; r < 4; r++) {
                    fma2(axw[r][0], Ar[r], b0.x);
                    fma2(axw[r][1], Ar[r], b0.y);
                    fma2(axw[r][2], Ar[r], b1.x);
                    fma2(axw[r][3], Ar[r], b1.y);
                }
            }
            __syncthreads();
        }
        float c1v[8];
#pragma unroll
        for (int t = 0; t < 4; t++) { c1v[t] = g_c1[p_j4 + t]; c1v[4 + t] = g_c1[64 + p_j4 + t]; }
#pragma unroll
        for (int r = 0; r < 4; r++) {
#pragma unroll
            for (int c = 0; c < 4; c++) {
                int col = (c < 2) ? (p_j4 + 2 * c) : (60 + p_j4 + 2 * c);
                float lo, hi;
                up2(axw[r][c], lo, hi);
                xws[(p_i0 + r) * 128 + col]     = lo + c1v[2 * c];
                xws[(p_i0 + r) * 128 + col + 1] = hi + c1v[2 * c + 1];
            }
        }
    }
    // zero states (overlays xck region; xws/buf/sB untouched)
    for (int i = tid; i < 15232; i += NTHR) sm[i] = 0.f;
    __syncthreads();

    float* cur = buf0;
    float* oth = buf1;

    // ---- step loop: 10 panel slots + 1 barrier ----
    for (int s = 0; s < steps; s++) {
        float4 pr[2];

        // L3 concat gemm: aA3 = [h2;h3] @ [W3T;-M3T],  aU3 = h3 @ U3T
        ull aA3[4] = {}, aU3[4] = {};
        // slot 0: L3 rows 0-63 (W3T)
        pld(g_L3 + 2048, tid, pr);
        gemmR4<64, 32, 8>(h2s, cur, i03, j3, aA3);
        pst(oth, tid, pr); __syncthreads();
        { float* t = cur; cur = oth; oth = t; }
        // slot 1: L3 rows 64-95 (-M3T) | U3T
        pld(g_W22T, tid, pr);
        gemmR4<32, 32, 8>(h3s, cur, i03, j3, aA3);
        gemmR4<32, 32, 8>(h3s, cur + 1024, i03, j3, aU3);
        pst(oth, tid, pr); __syncthreads();
        { float* t = cur; cur = oth; oth = t; }

        // ---- update h3 (all h3s reads done at slot-1 barrier) ----
        {
            float cc0 = sB[j3], cc1 = sB[j3 + 1];
            float ub0 = sB[32 + j3], ub1 = sB[32 + j3 + 1];
            float4 h0 = *reinterpret_cast<float4*>(h3s + j3 * P + i03);
            float4 h1v = *reinterpret_cast<float4*>(h3s + (j3 + 1) * P + i03);
#pragma unroll
            for (int r = 0; r < 4; r++) {
                float a0, a1, u0, u1;
                up2(aA3[r], a0, a1); up2(aU3[r], u0, u1);
                addf4(h0, r, ftanh(a0 + cc0) + ftanh(u0 + ub0));
                addf4(h1v, r, ftanh(a1 + cc1) + ftanh(u1 + ub1));
            }
            *reinterpret_cast<float4*>(h3s + j3 * P + i03) = h0;
            *reinterpret_cast<float4*>(h3s + (j3 + 1) * P + i03) = h1v;
        }

        // L2 concat gemm: aA2 = [h1;h2] @ [W2T;-M2T] (K=192), aU2 = h2 @ U2T (K=64)
        ull aA2[8] = {};
#pragma unroll 1
        for (int p = 0; p < 6; p++) {                     // slots 2-7
            const float* nx = (p < 5) ? (g_W22T + (p + 1) * 2048) : g_U2T;
            pld(nx, tid, pr);
            gemmR8<32, 64, 8>(h1s + 32 * p * P, cur, i0, j2, aA2);
            pst(oth, tid, pr); __syncthreads();
            float* t = cur; cur = oth; oth = t;
        }
        ull aU2[8] = {};
#pragma unroll 1
        for (int p = 0; p < 2; p++) {                     // slots 8-9
            const float* nx = p ? g_L3 : (g_U2T + 2048);
            pld(nx, tid, pr);
            gemmR8<32, 64, 8>(h2s + 32 * p * P, cur, i0, j2, aU2);
            pst(oth, tid, pr); __syncthreads();
            float* t = cur; cur = oth; oth = t;
        }

        // ---- update h2 (all h2s reads done at slot-9 barrier) ----
        {
            float cc0 = sB[64 + j2], cc1 = sB[64 + j2 + 1];
            float ub0 = sB[128 + j2], ub1 = sB[128 + j2 + 1];
            float4 ha0 = *reinterpret_cast<float4*>(h2s + j2 * P + i0);
            float4 ha1 = *reinterpret_cast<float4*>(h2s + j2 * P + i0 + 4);
            float4 hb0 = *reinterpret_cast<float4*>(h2s + (j2 + 1) * P + i0);
            float4 hb1 = *reinterpret_cast<float4*>(h2s + (j2 + 1) * P + i0 + 4);
#pragma unroll
            for (int r = 0; r < 8; r++) {
                float a0, a1, u0, u1;
                up2(aA2[r], a0, a1); up2(aU2[r], u0, u1);
                float d0 = ftanh(a0 + cc0) + ftanh(u0 + ub0);
                float d1 = ftanh(a1 + cc1) + ftanh(u1 + ub1);
                if (r < 4) { addf4(ha0, r, d0); addf4(hb0, r, d1); }
                else       { addf4(ha1, r - 4, d0); addf4(hb1, r - 4, d1); }
            }
            *reinterpret_cast<float4*>(h2s + j2 * P + i0)           = ha0;
            *reinterpret_cast<float4*>(h2s + j2 * P + i0 + 4)       = ha1;
            *reinterpret_cast<float4*>(h2s + (j2 + 1) * P + i0)     = hb0;
            *reinterpret_cast<float4*>(h2s + (j2 + 1) * P + i0 + 4) = hb1;
        }

        // ---- L1 dual gemm, B direct from global (L2-resident) ----
        ull aM1[8][2] = {}, aU1[8][2] = {};
        gemmL1G(h1s, g_M1T, g_U1T, i0, j4, aM1, aU1);
        __syncthreads();   // all h1s reads done before h1 writes

        // ---- update h1 ----
#pragma unroll
        for (int cp = 0; cp < 2; cp++) {
            int col = j4 + 2 * cp;
            float ub0 = sB[192 + col], ub1 = sB[192 + col + 1];
            float4 ha0 = *reinterpret_cast<float4*>(h1s + col * P + i0);
            float4 ha1 = *reinterpret_cast<float4*>(h1s + col * P + i0 + 4);
            float4 hb0 = *reinterpret_cast<float4*>(h1s + (col + 1) * P + i0);
            float4 hb1 = *reinterpret_cast<float4*>(h1s + (col + 1) * P + i0 + 4);
#pragma unroll
            for (int r = 0; r < 8; r++) {
                float m0, m1, u0, u1, xw0, xw1;
                up2(aM1[r][cp], m0, m1); up2(aU1[r][cp], u0, u1);
                up2(*reinterpret_cast<const ull*>(xws + (i0 + r) * 128 + col), xw0, xw1);
                float d0 = ftanh(xw0 + m0) + ftanh(u0 + ub0);
                float d1 = ftanh(xw1 + m1) + ftanh(u1 + ub1);
                if (r < 4) { addf4(ha0, r, d0); addf4(hb0, r, d1); }
                else       { addf4(ha1, r - 4, d0); addf4(hb1, r - 4, d1); }
            }
            *reinterpret_cast<float4*>(h1s + col * P + i0)           = ha0;
            *reinterpret_cast<float4*>(h1s + col * P + i0 + 4)       = ha1;
            *reinterpret_cast<float4*>(h1s + (col + 1) * P + i0)     = hb0;
            *reinterpret_cast<float4*>(h1s + (col + 1) * P + i0 + 4) = hb1;
        }
        // h1 writes ordered before next step's first h1s read (slot 2) by the
        // slot-0/slot-1 barriers; h2/h3 writes covered likewise.
    }
    __syncthreads();

    // ---- classifier: out = h3 @ clf^T + clf_b ----
    for (int idx = tid; idx < BT * 10; idx += NTHR) {
        int r = idx / 10, cc = idx - r * 10;
        float sacc = clfb[cc];
#pragma unroll
        for (int k = 0; k < 32; k++) sacc += h3s[k * P + r] * clfw[cc * 32 + k];
        out[(size_t)(row0 + r) * 10 + cc] = sacc;
    }
}

// ---------------- launch ----------------
extern "C" void kernel_launch(void* const* d_in, const int* in_sizes, int n_in,
                              void* d_out, int out_size) {
    const float* x    = (const float*)d_in[0];
    const float* W1w  = (const float*)d_in[1];
    const float* W1b  = (const float*)d_in[2];
    const float* U1w  = (const float*)d_in[3];
    const float* U1b  = (const float*)d_in[4];
    const float* W2w  = (const float*)d_in[5];
    const float* W2b  = (const float*)d_in[6];
    const float* U2w  = (const float*)d_in[7];
    const float* U2b  = (const float*)d_in[8];
    const float* W3w  = (const float*)d_in[9];
    const float* W3b  = (const float*)d_in[10];
    const float* U3w  = (const float*)d_in[11];
    const float* U3b  = (const float*)d_in[12];
    const float* fb3w = (const float*)d_in[13];
    const float* fb3b = (const float*)d_in[14];
    const float* fb2w = (const float*)d_in[15];
    const float* fb2b = (const float*)d_in[16];
    const float* fb1w = (const float*)d_in[17];
    const float* fb1b = (const float*)d_in[18];
    const float* clfw = (const float*)d_in[19];
    const float* clfb = (const float*)d_in[20];
    const int*   stp  = (const int*)d_in[21];

    int B = in_sizes[0] / 784;

    prep_all<<<256, 128>>>(W1w, W1b, U1w, W2w, W2b, U2w, W3w, W3b, U3w,
                           fb3w, fb3b, fb2w, fb2b, fb1w, fb1b);

    const int smem_bytes = 27840 * 4;   // 111360 -> 2 CTAs/SM
    cudaFuncSetAttribute(pcnet_main, cudaFuncAttributeMaxDynamicSharedMemorySize, smem_bytes);
    pcnet_main<<<B / BT, NTHR, smem_bytes>>>(x, U1b, U2b, U3b, clfw, clfb, stp, (float*)d_out);
}

// round 9
// speedup vs baseline: 1.0902x; 1.0902x over previous
#include <cuda_runtime.h>
#include <cstdint>

#define BT   64
#define P    68
#define NTHR 256
typedef unsigned long long ull;

// ---------------- persistent device scratch ----------------
__device__ __align__(16) float g_W1T[784*128];   // [k][j]
__device__ __align__(16) float g_L1P[32768];     // 8 pairs: [16][128] -M1T | [16][128] U1T
__device__ __align__(16) float g_W22T[192*64];   // rows 0-127: W2T, rows 128-191: -M2T
__device__ __align__(16) float g_U2T[64*64];
__device__ __align__(16) float g_L3[4096];       // W3T[64][32] | -M3T[32][32] | U3T[32][32]
__device__ __align__(16) float g_c1[128];
__device__ __align__(16) float g_c2[64];
__device__ __align__(16) float g_c3[32];
__device__ __align__(16) float g_XW[65536*128];  // xw, column-major per 64-row tile

// ---------------- helpers ----------------
__device__ __forceinline__ ull dup2(float x) {
    ull r; asm("mov.b64 %0, {%1, %1};" : "=l"(r) : "f"(x)); return r;
}
__device__ __forceinline__ void up2(ull v, float &lo, float &hi) {
    asm("mov.b64 {%0, %1}, %2;" : "=f"(lo), "=f"(hi) : "l"(v));
}
__device__ __forceinline__ void fma2(ull &d, ull a, ull b) {
    asm("fma.rn.f32x2 %0, %1, %2, %0;" : "+l"(d) : "l"(a), "l"(b));
}
// tanh(x) = 1 - 2/(1+e^{2x})  via MUFU.EX2 + MUFU.RCP (~1e-6 abs err)
__device__ __forceinline__ float ftanh(float x) {
    float e, r;
    asm("ex2.approx.ftz.f32 %0, %1;" : "=f"(e) : "f"(x * 2.8853900817779268f));
    asm("rcp.approx.ftz.f32 %0, %1;" : "=f"(r) : "f"(e + 1.0f));
    return fmaf(-2.0f, r, 1.0f);
}
__device__ __forceinline__ void addf4(float4 &v, int r, float d) {
    if (r == 0) v.x += d; else if (r == 1) v.y += d;
    else if (r == 2) v.z += d; else v.w += d;
}
__device__ __forceinline__ void setf4(float4 &v, int r, float d) {
    if (r == 0) v.x = d; else if (r == 1) v.y = d;
    else if (r == 2) v.z = d; else v.w = d;
}
__device__ __forceinline__ float getf4(const float4 &v, int r) {
    return (r == 0) ? v.x : (r == 1) ? v.y : (r == 2) ? v.z : v.w;
}

// L1 paired dual GEMM, K=16 panel: Bm = -M1T rows, Bu = U1T rows (each [16][128])
__device__ __forceinline__ void gemmL1(const float* __restrict__ A,
                                       const float* __restrict__ Bm,
                                       const float* __restrict__ Bu,
                                       int i0, int j4, ull (&m)[8][2], ull (&u)[8][2]) {
#pragma unroll
    for (int k = 0; k < 16; k++) {
        float4 a0 = *reinterpret_cast<const float4*>(A + k * P + i0);
        float4 a1 = *reinterpret_cast<const float4*>(A + k * P + i0 + 4);
        ulonglong2 bm = *reinterpret_cast<const ulonglong2*>(Bm + k * 128 + j4);
        ulonglong2 bu = *reinterpret_cast<const ulonglong2*>(Bu + k * 128 + j4);
        ull Ar[8] = {dup2(a0.x), dup2(a0.y), dup2(a0.z), dup2(a0.w),
                     dup2(a1.x), dup2(a1.y), dup2(a1.z), dup2(a1.w)};
#pragma unroll
        for (int r = 0; r < 8; r++) {
            fma2(m[r][0], Ar[r], bm.x);
            fma2(m[r][1], Ar[r], bm.y);
            fma2(u[r][0], Ar[r], bu.x);
            fma2(u[r][1], Ar[r], bu.y);
        }
    }
}

// 8 rows x 2 cols (1 f32x2) single-B GEMM, B in smem panel
template<int K, int LDB, int UNR>
__device__ __forceinline__ void gemmR8(const float* __restrict__ A,
                                       const float* __restrict__ B,
                                       int i0, int j, ull (&acc)[8]) {
#pragma unroll UNR
    for (int k = 0; k < K; k++) {
        float4 a0 = *reinterpret_cast<const float4*>(A + k * P + i0);
        float4 a1 = *reinterpret_cast<const float4*>(A + k * P + i0 + 4);
        ull b = *reinterpret_cast<const ull*>(B + k * LDB + j);
        ull Ar[8] = {dup2(a0.x), dup2(a0.y), dup2(a0.z), dup2(a0.w),
                     dup2(a1.x), dup2(a1.y), dup2(a1.z), dup2(a1.w)};
#pragma unroll
        for (int r = 0; r < 8; r++) fma2(acc[r], Ar[r], b);
    }
}

// 4 rows x 2 cols single-B GEMM
template<int K, int LDB, int UNR>
__device__ __forceinline__ void gemmR4(const float* __restrict__ A,
                                       const float* __restrict__ B,
                                       int i0, int j, ull (&acc)[4]) {
#pragma unroll UNR
    for (int k = 0; k < K; k++) {
        float4 a = *reinterpret_cast<const float4*>(A + k * P + i0);
        ull b = *reinterpret_cast<const ull*>(B + k * LDB + j);
        ull Ar[4] = {dup2(a.x), dup2(a.y), dup2(a.z), dup2(a.w)};
#pragma unroll
        for (int r = 0; r < 4; r++) fma2(acc[r], Ar[r], b);
    }
}

// 4096-float panel staging: 4 float4 per thread
__device__ __forceinline__ void pld4(const float* __restrict__ src, int tid, float4 (&r)[4]) {
#pragma unroll
    for (int j = 0; j < 4; j++)
        r[j] = *reinterpret_cast<const float4*>(src + j * 1024 + tid * 4);
}
__device__ __forceinline__ void pst4(float* dst, int tid, const float4 (&r)[4]) {
#pragma unroll
    for (int j = 0; j < 4; j++)
        *reinterpret_cast<float4*>(dst + j * 1024 + tid * 4) = r[j];
}

// ---------------- prep kernel ----------------
__global__ void prep_all(const float* __restrict__ W1w, const float* __restrict__ W1b,
                         const float* __restrict__ U1w,
                         const float* __restrict__ W2w, const float* __restrict__ W2b,
                         const float* __restrict__ U2w,
                         const float* __restrict__ W3w, const float* __restrict__ W3b,
                         const float* __restrict__ U3w,
                         const float* __restrict__ fb3w, const float* __restrict__ fb3b,
                         const float* __restrict__ fb2w, const float* __restrict__ fb2b,
                         const float* __restrict__ fb1w, const float* __restrict__ fb1b) {
    __shared__ float row_s[784];
    __shared__ float red_s[128];
    const int bid = blockIdx.x;
    const int tid = threadIdx.x;   // 128

    if (bid < 128) {
        const int j = bid;
        for (int d = tid; d < 784; d += 128) row_s[d] = W1w[j * 784 + d];
        __syncthreads();
        {
            const int k = tid;
            float s = 0.f;
#pragma unroll 4
            for (int d = 0; d < 784; d++) s += row_s[d] * fb1w[d * 128 + k];
            g_L1P[(k >> 4) * 4096 + (k & 15) * 128 + j] = -s;   // -M1T pair layout
        }
        float ps = 0.f;
        for (int d = tid; d < 784; d += 128) ps += row_s[d] * fb1b[d];
        red_s[tid] = ps;
        __syncthreads();
        for (int off = 64; off > 0; off >>= 1) {
            if (tid < off) red_s[tid] += red_s[tid + off];
            __syncthreads();
        }
        if (tid == 0) g_c1[j] = W1b[j] - red_s[0];
    } else if (bid < 192) {
        const int j = bid - 128;
        for (int d = tid; d < 128; d += 128) row_s[d] = W2w[j * 128 + d];
        __syncthreads();
        if (tid < 64) {
            const int k = tid;
            float s = 0.f;
#pragma unroll 4
            for (int d = 0; d < 128; d++) s += row_s[d] * fb2w[d * 64 + k];
            g_W22T[(128 + k) * 64 + j] = -s;   // -M2T rows of stacked weight
        }
        float ps = 0.f;
        for (int d = tid; d < 128; d += 128) ps += row_s[d] * fb2b[d];
        red_s[tid] = ps;
        __syncthreads();
        for (int off = 64; off > 0; off >>= 1) {
            if (tid < off) red_s[tid] += red_s[tid + off];
            __syncthreads();
        }
        if (tid == 0) g_c2[j] = W2b[j] - red_s[0];
    } else if (bid < 224) {
        const int j = bid - 192;
        for (int d = tid; d < 64; d += 128) row_s[d] = W3w[j * 64 + d];
        __syncthreads();
        if (tid < 32) {
            const int k = tid;
            float s = 0.f;
#pragma unroll 4
            for (int d = 0; d < 64; d++) s += row_s[d] * fb3w[d * 32 + k];
            g_L3[(64 + k) * 32 + j] = -s;    // -M3T rows of stacked weight
        }
        float ps = 0.f;
        for (int d = tid; d < 64; d += 128) ps += row_s[d] * fb3b[d];
        red_s[tid] = ps;
        __syncthreads();
        for (int off = 64; off > 0; off >>= 1) {
            if (tid < off) red_s[tid] += red_s[tid + off];
            __syncthreads();
        }
        if (tid == 0) g_c3[j] = W3b[j] - red_s[0];
    } else {
        const int idx0 = (bid - 224) * 128 + tid;
        const int stride = 32 * 128;
        for (int t = idx0; t < 784 * 128; t += stride) {
            int k = t >> 7, j = t & 127;
            g_W1T[t] = W1w[j * 784 + k];
        }
        for (int t = idx0; t < 128 * 128; t += stride) {          // U1T pair layout
            int k = t >> 7, j = t & 127;
            g_L1P[(k >> 4) * 4096 + 2048 + (k & 15) * 128 + j] = U1w[j * 128 + k];
        }
        for (int t = idx0; t < 128 * 64; t += stride) {           // W2T rows of stacked
            int k = t >> 6, j = t & 63;
            g_W22T[t] = W2w[j * 128 + k];
        }
        for (int t = idx0; t < 64 * 64; t += stride) {
            int k = t >> 6, j = t & 63;
            g_U2T[t] = U2w[j * 64 + k];
        }
        for (int t = idx0; t < 64 * 32; t += stride) {            // W3T rows of stacked
            int k = t >> 5, j = t & 31;
            g_L3[t] = W3w[j * 64 + k];
        }
        for (int t = idx0; t < 32 * 32; t += stride) {            // U3T
            int k = t >> 5, j = t & 31;
            g_L3[3072 + t] = U3w[j * 32 + k];
        }
    }
}

// ---------------- main kernel ----------------
// smem floats (23744 = 94976 B, 2 CTAs/SM):
//   h1s[128*68]@0  h2s[64*68]@8704  h3s[32*68]@13056   (states end 15232)
//   buf0@15232(4096)  buf1@19328(4096)  sB@23424(320)
// phase-1 overlay: xck@0 [64][116]=7424, wck@7424 [112][128] (ends 21760).
// buf0/buf1 are only filled AFTER phase 1; sB (23424+) is beyond the overlay.
__global__ void __launch_bounds__(NTHR, 2)
pcnet_main(const float* __restrict__ x,
           const float* __restrict__ U1b, const float* __restrict__ U2b,
           const float* __restrict__ U3b,
           const float* __restrict__ clfw, const float* __restrict__ clfb,
           const int* __restrict__ steps_p,
           float* __restrict__ out) {
    extern __shared__ float sm[];
    float* h1s  = sm;
    float* h2s  = sm + 8704;
    float* h3s  = sm + 13056;
    float* buf0 = sm + 15232;
    float* buf1 = sm + 19328;
    float* sB   = sm + 23424;
    float* xck  = sm;           // overlay
    float* wck  = sm + 7424;    // overlay

    const int tid  = threadIdx.x;
    const int row0 = blockIdx.x * BT;
    float* const xwg = g_XW + (size_t)blockIdx.x * 8192;   // [128 cols][64 rows]

    // tile mapping: warp spans 4 row-groups x 8 col-quads
    const int wid  = tid >> 5, lane = tid & 31;
    const int rg   = ((wid & 1) << 2) + (lane >> 3);   // 0..7
    const int cq   = ((wid >> 1) << 3) + (lane & 7);   // 0..31
    const int i0   = rg * 8;
    const int j4   = cq * 4;      // L1 cols
    const int j2   = cq * 2;      // L2 cols
    const int rg3  = ((wid & 3) << 2) + (lane >> 3);   // 0..15
    const int cq3  = ((wid >> 2) << 3) + (lane & 7);   // 0..15
    const int i03  = rg3 * 4;
    const int j3   = cq3 * 2;     // L3 cols

    int steps = *steps_p;
    if (steps < 0 || steps > 64) steps = 5;

    // stage biases (region beyond phase-1 overlay)
    for (int t = tid; t < 320; t += NTHR) {
        float v;
        if (t < 32) v = g_c3[t];
        else if (t < 64) v = U3b[t - 32];
        else if (t < 128) v = g_c2[t - 64];
        else if (t < 192) v = U2b[t - 128];
        else v = U1b[t - 192];
        sB[t] = v;
    }

    // ---- phase 1: xw = x @ W1^T + c1 -> g_XW (column-major per tile) ----
    {
        const int p_i0 = (tid >> 4) * 4;
        const int p_j4 = (tid & 15) * 4;
        ull axw[4][4] = {};
        for (int c = 0; c < 7; c++) {
            for (int idx = tid; idx < 64 * 28; idx += NTHR) {
                int r = idx / 28, k4 = idx - r * 28;
                *reinterpret_cast<float4*>(xck + r * 116 + k4 * 4) =
                    *reinterpret_cast<const float4*>(x + (size_t)(row0 + r) * 784 + c * 112 + k4 * 4);
            }
            for (int idx = tid; idx < 112 * 32; idx += NTHR) {
                int kk = idx >> 5, jj = idx & 31;
                *reinterpret_cast<float4*>(wck + kk * 128 + jj * 4) =
                    *reinterpret_cast<const float4*>(g_W1T + (size_t)(c * 112 + kk) * 128 + jj * 4);
            }
            __syncthreads();
#pragma unroll 2
            for (int kk = 0; kk < 112; kk++) {
                ulonglong2 b0 = *reinterpret_cast<const ulonglong2*>(wck + kk * 128 + p_j4);
                ulonglong2 b1 = *reinterpret_cast<const ulonglong2*>(wck + kk * 128 + 64 + p_j4);
                ull Ar[4] = {dup2(xck[(p_i0 + 0) * 116 + kk]), dup2(xck[(p_i0 + 1) * 116 + kk]),
                             dup2(xck[(p_i0 + 2) * 116 + kk]), dup2(xck[(p_i0 + 3) * 116 + kk])};
#pragma unroll
                for (int r = 0; r < 4; r++) {
                    fma2(axw[r][0], Ar[r], b0.x);
                    fma2(axw[r][1], Ar[r], b0.y);
                    fma2(axw[r][2], Ar[r], b1.x);
                    fma2(axw[r][3], Ar[r], b1.y);
                }
            }
            __syncthreads();
        }
        float c1v[8];
#pragma unroll
        for (int t = 0; t < 4; t++) { c1v[t] = g_c1[p_j4 + t]; c1v[4 + t] = g_c1[64 + p_j4 + t]; }
#pragma unroll
        for (int c = 0; c < 4; c++) {
            int col = (c < 2) ? (p_j4 + 2 * c) : (60 + p_j4 + 2 * c);
            float4 v0, v1;
#pragma unroll
            for (int r = 0; r < 4; r++) {
                float lo, hi;
                up2(axw[r][c], lo, hi);
                setf4(v0, r, lo + c1v[2 * c]);
                setf4(v1, r, hi + c1v[2 * c + 1]);
            }
            *reinterpret_cast<float4*>(xwg + col * 64 + p_i0)       = v0;
            *reinterpret_cast<float4*>(xwg + (col + 1) * 64 + p_i0) = v1;
        }
    }
    __syncthreads();   // phase-1 overlay reads done; xw STGs ordered before step reads
    // zero states, preload first panel
    for (int i = tid; i < 15232; i += NTHR) sm[i] = 0.f;
    for (int idx = tid; idx < 1024; idx += NTHR)
        *reinterpret_cast<float4*>(buf0 + idx * 4) = *reinterpret_cast<const float4*>(g_L3 + idx * 4);
    __syncthreads();

    float* cur = buf0;
    float* oth = buf1;

    // ---- step loop: 13 panel slots ----
    for (int s = 0; s < steps; s++) {
        float4 pr[4];

        // slot 0: L3 full panel (W3T | -M3T | U3T)
        ull aA3[4] = {}, aU3[4] = {};
        pld4(g_W22T, tid, pr);
        gemmR4<64, 32, 8>(h2s, cur, i03, j3, aA3);
        gemmR4<32, 32, 8>(h3s, cur + 2048, i03, j3, aA3);
        gemmR4<32, 32, 8>(h3s, cur + 3072, i03, j3, aU3);
        pst4(oth, tid, pr); __syncthreads();
        { float* t = cur; cur = oth; oth = t; }

        // ---- update h3 ----
        {
            float cc0 = sB[j3], cc1 = sB[j3 + 1];
            float ub0 = sB[32 + j3], ub1 = sB[32 + j3 + 1];
            float4 h0 = *reinterpret_cast<float4*>(h3s + j3 * P + i03);
            float4 h1v = *reinterpret_cast<float4*>(h3s + (j3 + 1) * P + i03);
#pragma unroll
            for (int r = 0; r < 4; r++) {
                float a0, a1, u0, u1;
                up2(aA3[r], a0, a1); up2(aU3[r], u0, u1);
                addf4(h0, r, ftanh(a0 + cc0) + ftanh(u0 + ub0));
                addf4(h1v, r, ftanh(a1 + cc1) + ftanh(u1 + ub1));
            }
            *reinterpret_cast<float4*>(h3s + j3 * P + i03) = h0;
            *reinterpret_cast<float4*>(h3s + (j3 + 1) * P + i03) = h1v;
        }

        // slots 1-3: concat [h1;h2] @ [W2T;-M2T], K=64 per slot
        ull aA2[8] = {};
#pragma unroll
        for (int p = 0; p < 3; p++) {
            const float* Ap = (p == 0) ? h1s : (p == 1) ? (h1s + 64 * P) : h2s;
            const float* nx = (p < 2) ? (g_W22T + (p + 1) * 4096) : g_U2T;
            pld4(nx, tid, pr);
            gemmR8<64, 64, 8>(Ap, cur, i0, j2, aA2);
            pst4(oth, tid, pr); __syncthreads();
            float* t = cur; cur = oth; oth = t;
        }
        // slot 4: U2T (K=64)
        ull aU2[8] = {};
        pld4(g_L1P, tid, pr);
        gemmR8<64, 64, 8>(h2s, cur, i0, j2, aU2);
        pst4(oth, tid, pr); __syncthreads();
        { float* t = cur; cur = oth; oth = t; }

        // ---- update h2 ----
        {
            float cc0 = sB[64 + j2], cc1 = sB[64 + j2 + 1];
            float ub0 = sB[128 + j2], ub1 = sB[128 + j2 + 1];
            float4 ha0 = *reinterpret_cast<float4*>(h2s + j2 * P + i0);
            float4 ha1 = *reinterpret_cast<float4*>(h2s + j2 * P + i0 + 4);
            float4 hb0 = *reinterpret_cast<float4*>(h2s + (j2 + 1) * P + i0);
            float4 hb1 = *reinterpret_cast<float4*>(h2s + (j2 + 1) * P + i0 + 4);
#pragma unroll
            for (int r = 0; r < 8; r++) {
                float a0, a1, u0, u1;
                up2(aA2[r], a0, a1); up2(aU2[r], u0, u1);
                float d0 = ftanh(a0 + cc0) + ftanh(u0 + ub0);
                float d1 = ftanh(a1 + cc1) + ftanh(u1 + ub1);
                if (r < 4) { addf4(ha0, r, d0); addf4(hb0, r, d1); }
                else       { addf4(ha1, r - 4, d0); addf4(hb1, r - 4, d1); }
            }
            *reinterpret_cast<float4*>(h2s + j2 * P + i0)           = ha0;
            *reinterpret_cast<float4*>(h2s + j2 * P + i0 + 4)       = ha1;
            *reinterpret_cast<float4*>(h2s + (j2 + 1) * P + i0)     = hb0;
            *reinterpret_cast<float4*>(h2s + (j2 + 1) * P + i0 + 4) = hb1;
        }

        // slots 5-12: L1 paired panels (-M1T | U1T), K=16 each
        ull aM1[8][2] = {}, aU1[8][2] = {};
#pragma unroll 1
        for (int p = 0; p < 8; p++) {
            const float* nx = (p < 7) ? (g_L1P + (p + 1) * 4096) : g_L3;
            pld4(nx, tid, pr);
            gemmL1(h1s + 16 * p * P, cur, cur + 2048, i0, j4, aM1, aU1);
            pst4(oth, tid, pr); __syncthreads();
            float* t = cur; cur = oth; oth = t;
        }

        // ---- update h1 (xw streamed from L2-resident g_XW, column-major) ----
#pragma unroll
        for (int cp = 0; cp < 2; cp++) {
            int col = j4 + 2 * cp;
            float ub0 = sB[192 + col], ub1 = sB[192 + col + 1];
            float4 xa0 = *reinterpret_cast<const float4*>(xwg + col * 64 + i0);
            float4 xa1 = *reinterpret_cast<const float4*>(xwg + col * 64 + i0 + 4);
            float4 xb0 = *reinterpret_cast<const float4*>(xwg + (col + 1) * 64 + i0);
            float4 xb1 = *reinterpret_cast<const float4*>(xwg + (col + 1) * 64 + i0 + 4);
            float4 ha0 = *reinterpret_cast<float4*>(h1s + col * P + i0);
            float4 ha1 = *reinterpret_cast<float4*>(h1s + col * P + i0 + 4);
            float4 hb0 = *reinterpret_cast<float4*>(h1s + (col + 1) * P + i0);
            float4 hb1 = *reinterpret_cast<float4*>(h1s + (col + 1) * P + i0 + 4);
#pragma unroll
            for (int r = 0; r < 8; r++) {
                float m0, m1, u0, u1;
                up2(aM1[r][cp], m0, m1); up2(aU1[r][cp], u0, u1);
                float xw0 = (r < 4) ? getf4(xa0, r) : getf4(xa1, r - 4);
                float xw1 = (r < 4) ? getf4(xb0, r) : getf4(xb1, r - 4);
                float d0 = ftanh(xw0 + m0) + ftanh(u0 + ub0);
                float d1 = ftanh(xw1 + m1) + ftanh(u1 + ub1);
                if (r < 4) { addf4(ha0, r, d0); addf4(hb0, r, d1); }
                else       { addf4(ha1, r - 4, d0); addf4(hb1, r - 4, d1); }
            }
            *reinterpret_cast<float4*>(h1s + col * P + i0)           = ha0;
            *reinterpret_cast<float4*>(h1s + col * P + i0 + 4)       = ha1;
            *reinterpret_cast<float4*>(h1s + (col + 1) * P + i0)     = hb0;
            *reinterpret_cast<float4*>(h1s + (col + 1) * P + i0 + 4) = hb1;
        }
        // h1 writes ordered before next step's first h1s read (slot 1) by the
        // next step's slot-0 barrier; h2/h3 writes covered likewise.
    }
    __syncthreads();

    // ---- classifier: out = h3 @ clf^T + clf_b ----
    for (int idx = tid; idx < BT * 10; idx += NTHR) {
        int r = idx / 10, cc = idx - r * 10;
        float sacc = clfb[cc];
#pragma unroll
        for (int k = 0; k < 32; k++) sacc += h3s[k * P + r] * clfw[cc * 32 + k];
        out[(size_t)(row0 + r) * 10 + cc] = sacc;
    }
}

// ---------------- launch ----------------
extern "C" void kernel_launch(void* const* d_in, const int* in_sizes, int n_in,
                              void* d_out, int out_size) {
    const float* x    = (const float*)d_in[0];
    const float* W1w  = (const float*)d_in[1];
    const float* W1b  = (const float*)d_in[2];
    const float* U1w  = (const float*)d_in[3];
    const float* U1b  = (const float*)d_in[4];
    const float* W2w  = (const float*)d_in[5];
    const float* W2b  = (const float*)d_in[6];
    const float* U2w  = (const float*)d_in[7];
    const float* U2b  = (const float*)d_in[8];
    const float* W3w  = (const float*)d_in[9];
    const float* W3b  = (const float*)d_in[10];
    const float* U3w  = (const float*)d_in[11];
    const float* U3b  = (const float*)d_in[12];
    const float* fb3w = (const float*)d_in[13];
    const float* fb3b = (const float*)d_in[14];
    const float* fb2w = (const float*)d_in[15];
    const float* fb2b = (const float*)d_in[16];
    const float* fb1w = (const float*)d_in[17];
    const float* fb1b = (const float*)d_in[18];
    const float* clfw = (const float*)d_in[19];
    const float* clfb = (const float*)d_in[20];
    const int*   stp  = (const int*)d_in[21];

    int B = in_sizes[0] / 784;
    if (B > 65536) B = 65536;   // g_XW capacity guard

    prep_all<<<256, 128>>>(W1w, W1b, U1w, W2w, W2b, U2w, W3w, W3b, U3w,
                           fb3w, fb3b, fb2w, fb2b, fb1w, fb1b);

    const int smem_bytes = 23744 * 4;   // 94976 -> 2 CTAs/SM
    cudaFuncSetAttribute(pcnet_main, cudaFuncAttributeMaxDynamicSharedMemorySize, smem_bytes);
    pcnet_main<<<B / BT, NTHR, smem_bytes>>>(x, U1b, U2b, U3b, clfw, clfb, stp, (float*)d_out);
}